// round 1
// baseline (speedup 1.0000x reference)
#include <cuda_runtime.h>
#include <cuda_bf16.h>

// Capsule routing, fused factorization (u_hat never materialized).
// Shapes: u (B=32, I=1024, C=256) fp32; W (C=256, N*D=2048) fp32; out (B, N=32, D=64) fp32.
//
// Pipeline:
//   s0[b,c]   = (1/32) * sum_i u[b,i,c]                      (colsum, iter-0 uniform softmax)
//   out0      = squash(s0 @ W_n)            + V0 = out0 @ W_n^T
//   repeat 2x:
//     blog[b,n,i] = sum_c V[b,n,c] u[b,i,c]
//     c = softmax_n(blog)
//     S[b,n,c]    = sum_i c[b,n,i] u[b,i,c]
//     out = squash(S @ W_n)  (+ V = out @ W_n^T, except final)
//
// FLOPs ~ 1.1 GFMA, DRAM ~160 MB.  All scratch in __device__ globals (no allocs).

#define BB 32
#define II 1024
#define CC 256
#define NN 32
#define DD 64
#define ND 2048   // NN*DD

__device__ float g_part[BB * 8 * CC];     // colsum partials
__device__ float g_s0[BB * CC];           // iter-0 weighted sum
__device__ float g_S[BB * NN * CC];       // S[b][n][c]
__device__ float g_V[BB * NN * CC];       // V[b][n][c]
__device__ float g_blog[BB * NN * II];    // logits -> softmax in place

// ---------------------------------------------------------------------------
// colsum partials: g_part[(b*8+q)][c] = sum over 128 i of u[b][i][c]
__global__ void k_colsum_part(const float* __restrict__ u) {
    int q = blockIdx.x;          // 0..7
    int b = blockIdx.y;          // 0..31
    int c = threadIdx.x;         // 0..255
    const float* p = u + (size_t)b * II * CC + (size_t)q * 128 * CC + c;
    float s = 0.f;
#pragma unroll 8
    for (int i = 0; i < 128; i++) s += p[(size_t)i * CC];
    g_part[(b * 8 + q) * CC + c] = s;
}

__global__ void k_colsum_reduce() {
    int b = blockIdx.x;
    int c = threadIdx.x;
    float s = 0.f;
#pragma unroll
    for (int q = 0; q < 8; q++) s += g_part[(b * 8 + q) * CC + c];
    g_s0[b * CC + c] = s * (1.0f / 32.0f);
}

// ---------------------------------------------------------------------------
// Capsule projection + squash (+ optional V).
// block: (n, b), 256 threads.
//  mode 0: S row = g_s0[b] (uniform pass), compute V
//  mode 1: S row = g_S[b][n],              compute V
//  mode 2: S row = g_S[b][n], write dout,  skip V
__global__ void k_caps(const float* __restrict__ W, int mode, float* __restrict__ dout) {
    __shared__ float sS[CC];
    __shared__ float sOut[DD];
    __shared__ float sRed[256];
    __shared__ float sWarp[8];
    int n = blockIdx.x, b = blockIdx.y;
    int t = threadIdx.x, lane = t & 31, w = t >> 5;

    sS[t] = (mode == 0) ? g_s0[b * CC + t] : g_S[(b * NN + n) * CC + t];
    __syncthreads();

    // phase A: out_raw[d] = sum_c sS[c] * W[c][n*64+d]
    int d = t & 63, cq = t >> 6;                     // 4 c-quarters x 64 d
    const float* Wp = W + n * DD + d;
    float a = 0.f;
#pragma unroll 8
    for (int cc = 0; cc < 64; cc++) {
        int c = cq * 64 + cc;
        a += sS[c] * Wp[(size_t)c * ND];
    }
    sRed[t] = a;
    __syncthreads();

    float val = 0.f;
    if (t < 64) val = sRed[t] + sRed[t + 64] + sRed[t + 128] + sRed[t + 192];
    float sq = val * val;
#pragma unroll
    for (int off = 16; off; off >>= 1) sq += __shfl_xor_sync(0xffffffffu, sq, off);
    if (lane == 0) sWarp[w] = sq;
    __syncthreads();
    float ss = 0.f;
#pragma unroll
    for (int r = 0; r < 8; r++) ss += sWarp[r];
    float o = val * rsqrtf(ss + 1e-7f);   // squash: x / sqrt(sum(x^2) + eps)
    if (t < 64) {
        sOut[t] = o;
        if (mode == 2) dout[(b * NN + n) * DD + t] = o;
    }
    if (mode == 2) return;   // uniform across block
    __syncthreads();

    // phase B: V[b][n][c] = sum_d sOut[d] * W[c][n*64+d]   (thread = c)
    const float4* Wv = (const float4*)(W + (size_t)t * ND + n * DD);
    float vv = 0.f;
#pragma unroll
    for (int j = 0; j < 16; j++) {
        float4 w4 = Wv[j];
        vv += w4.x * sOut[4 * j] + w4.y * sOut[4 * j + 1] +
              w4.z * sOut[4 * j + 2] + w4.w * sOut[4 * j + 3];
    }
    g_V[(b * NN + n) * CC + t] = vv;
}

// ---------------------------------------------------------------------------
// blog[b][n][i] = sum_c V[b][n][c] * u[b][i][c]
// grid (8 i-chunks, B), 256 threads. Output tile 32n x 128i, thread tile 4x4.
// warp w owns n in {w, w+8, w+16, w+24}; lane owns i in {i0+lane+32q}.
__global__ void k_blog(const float* __restrict__ u) {
    __shared__ float sA[32][33];     // V[n][k] slice
    __shared__ float sB[32][129];    // U[k][i] transposed slice
    int b = blockIdx.y;
    int i0 = blockIdx.x * 128;
    int t = threadIdx.x, lane = t & 31, w = t >> 5;
    const float* Ub = u + (size_t)b * II * CC;
    const float* Vb = g_V + (size_t)(b * NN) * CC;

    float acc[16];
#pragma unroll
    for (int x = 0; x < 16; x++) acc[x] = 0.f;

    for (int kb = 0; kb < CC; kb += 32) {
        __syncthreads();
#pragma unroll
        for (int r = 0; r < 4; r++)
            sA[w + 8 * r][lane] = Vb[(w + 8 * r) * CC + kb + lane];
#pragma unroll
        for (int r = 0; r < 16; r++) {
            int i = w + 8 * r;   // same i across the warp; lane = k
            sB[lane][i] = Ub[(size_t)(i0 + i) * CC + kb + lane];
        }
        __syncthreads();
#pragma unroll
        for (int k2 = 0; k2 < 32; k2++) {
            float a0 = sA[w][k2], a1 = sA[w + 8][k2], a2 = sA[w + 16][k2], a3 = sA[w + 24][k2];
            float b0 = sB[k2][lane], b1 = sB[k2][lane + 32],
                  b2 = sB[k2][lane + 64], b3 = sB[k2][lane + 96];
            acc[0]  += a0 * b0; acc[1]  += a0 * b1; acc[2]  += a0 * b2; acc[3]  += a0 * b3;
            acc[4]  += a1 * b0; acc[5]  += a1 * b1; acc[6]  += a1 * b2; acc[7]  += a1 * b3;
            acc[8]  += a2 * b0; acc[9]  += a2 * b1; acc[10] += a2 * b2; acc[11] += a2 * b3;
            acc[12] += a3 * b0; acc[13] += a3 * b1; acc[14] += a3 * b2; acc[15] += a3 * b3;
        }
    }
    float* Bb = g_blog + (size_t)(b * NN) * II;
#pragma unroll
    for (int p = 0; p < 4; p++)
#pragma unroll
        for (int q = 0; q < 4; q++)
            Bb[(w + 8 * p) * II + i0 + lane + 32 * q] = acc[p * 4 + q];
}

// ---------------------------------------------------------------------------
// softmax over n (32 values, stride II) in place on g_blog
__global__ void k_softmax() {
    int g = blockIdx.x * blockDim.x + threadIdx.x;   // 0..32767 = B*I
    int b = g >> 10;
    int i = g & 1023;
    float* p = g_blog + (size_t)(b * NN) * II + i;
    float v[32];
    float m = -1e30f;
#pragma unroll
    for (int n = 0; n < 32; n++) { v[n] = p[n * II]; m = fmaxf(m, v[n]); }
    float s = 0.f;
#pragma unroll
    for (int n = 0; n < 32; n++) { v[n] = __expf(v[n] - m); s += v[n]; }
    float inv = 1.0f / s;
#pragma unroll
    for (int n = 0; n < 32; n++) p[n * II] = v[n] * inv;
}

// ---------------------------------------------------------------------------
__global__ void k_zeroS() { g_S[blockIdx.x * 1024 + threadIdx.x] = 0.f; }

// S[b][n][c] = sum_i c[b][n][i] * u[b][i][c]
// grid (2 c-chunks, 4 k-splits, B), 256 threads. Tile 32n x 128c, thread 4x4.
__global__ void k_sgemm(const float* __restrict__ u) {
    __shared__ float sA[32][33];     // c[n][k] slice
    __shared__ float sB[32][129];    // U[k][c] slice (natural layout)
    int b = blockIdx.z;
    int c0 = blockIdx.x * 128;
    int kOff = blockIdx.y * 256;
    int t = threadIdx.x, lane = t & 31, w = t >> 5;
    const float* Ub = u + (size_t)b * II * CC;
    const float* Cb = g_blog + (size_t)(b * NN) * II;

    float acc[16];
#pragma unroll
    for (int x = 0; x < 16; x++) acc[x] = 0.f;

    for (int kb = 0; kb < 256; kb += 32) {
        __syncthreads();
#pragma unroll
        for (int r = 0; r < 4; r++)
            sA[w + 8 * r][lane] = Cb[(w + 8 * r) * II + kOff + kb + lane];
        {
            int ci = t & 127;
            int kr = t >> 7;         // 0..1, two k-rows per pass
#pragma unroll
            for (int r = 0; r < 16; r++) {
                int k = kr + 2 * r;
                sB[k][ci] = Ub[(size_t)(kOff + kb + k) * CC + c0 + ci];
            }
        }
        __syncthreads();
#pragma unroll
        for (int k2 = 0; k2 < 32; k2++) {
            float a0 = sA[w][k2], a1 = sA[w + 8][k2], a2 = sA[w + 16][k2], a3 = sA[w + 24][k2];
            float b0 = sB[k2][lane], b1 = sB[k2][lane + 32],
                  b2 = sB[k2][lane + 64], b3 = sB[k2][lane + 96];
            acc[0]  += a0 * b0; acc[1]  += a0 * b1; acc[2]  += a0 * b2; acc[3]  += a0 * b3;
            acc[4]  += a1 * b0; acc[5]  += a1 * b1; acc[6]  += a1 * b2; acc[7]  += a1 * b3;
            acc[8]  += a2 * b0; acc[9]  += a2 * b1; acc[10] += a2 * b2; acc[11] += a2 * b3;
            acc[12] += a3 * b0; acc[13] += a3 * b1; acc[14] += a3 * b2; acc[15] += a3 * b3;
        }
    }
#pragma unroll
    for (int p = 0; p < 4; p++)
#pragma unroll
        for (int q = 0; q < 4; q++)
            atomicAdd(&g_S[(b * NN + w + 8 * p) * CC + c0 + lane + 32 * q], acc[p * 4 + q]);
}

// ---------------------------------------------------------------------------
extern "C" void kernel_launch(void* const* d_in, const int* in_sizes, int n_in,
                              void* d_out, int out_size) {
    const float* u = (const float*)d_in[0];
    const float* W = (const float*)d_in[1];
    if (n_in >= 2 && in_sizes[0] == CC * ND) {   // defensive: swap if order differs
        u = (const float*)d_in[1];
        W = (const float*)d_in[0];
    }
    float* out = (float*)d_out;

    k_colsum_part<<<dim3(8, BB), 256>>>(u);
    k_colsum_reduce<<<BB, 256>>>();
    k_caps<<<dim3(NN, BB), 256>>>(W, 0, nullptr);        // outputs0 -> V0

    for (int pass = 0; pass < 2; pass++) {
        k_blog<<<dim3(8, BB), 256>>>(u);                  // logits from V
        k_softmax<<<128, 256>>>();                        // c = softmax_n
        k_zeroS<<<256, 1024>>>();
        k_sgemm<<<dim3(2, 4, BB), 256>>>(u);              // S = c @ U
        if (pass == 0)
            k_caps<<<dim3(NN, BB), 256>>>(W, 1, nullptr); // outputs1 -> V1
        else
            k_caps<<<dim3(NN, BB), 256>>>(W, 2, out);     // final outputs
    }
}

// round 3
// speedup vs baseline: 1.0128x; 1.0128x over previous
#include <cuda_runtime.h>
#include <cuda_bf16.h>

// Capsule routing, fused factorization + f32x2 packed FMA.
// u (32,1024,256) f32; W (256,2048) f32; out (32,32,64) f32.
//
//   s0 = colsum(u)/32 ; out0 = squash(s0 @ W_n); V0 = out0 @ W_n^T
//   2x: [fused] blog = V @ U^T -> softmax_n -> Spart = c @ U
//       [caps]  out = squash(sum(Spart) @ W_n); V = out @ W_n^T (except last)

#define BB 32
#define II 1024
#define CC 256
#define NN 32
#define DD 64
#define ND 2048

typedef unsigned long long ull;

__device__ float g_part[BB * 8 * CC];
__device__ float g_s0[BB * CC];
__device__ float g_V[BB * NN * CC];
__device__ float g_Spart[BB * 8 * NN * CC];   // split-K partials of S

// ---- f32x2 helpers -------------------------------------------------------
__device__ __forceinline__ ull pack2(float x) {
    ull r; unsigned xi = __float_as_uint(x);
    asm("mov.b64 %0, {%1, %1};" : "=l"(r) : "r"(xi));
    return r;
}
__device__ __forceinline__ ull pack2b(float x, float y) {
    ull r; unsigned xi = __float_as_uint(x), yi = __float_as_uint(y);
    asm("mov.b64 %0, {%1, %2};" : "=l"(r) : "r"(xi), "r"(yi));
    return r;
}
__device__ __forceinline__ void fma2(ull& d, ull a, ull b) {
    asm("fma.rn.f32x2 %0, %1, %2, %0;" : "+l"(d) : "l"(a), "l"(b));
}
__device__ __forceinline__ float2 unpack2(ull p) {
    unsigned lo, hi;
    asm("mov.b64 {%0, %1}, %2;" : "=r"(lo), "=r"(hi) : "l"(p));
    return make_float2(__uint_as_float(lo), __uint_as_float(hi));
}

// ---- colsum (iter-0 uniform softmax) ------------------------------------
__global__ void k_colsum_part(const float* __restrict__ u) {
    int q = blockIdx.x, b = blockIdx.y, c = threadIdx.x;
    const float* p = u + (size_t)b * II * CC + (size_t)q * 128 * CC + c;
    float s = 0.f;
#pragma unroll 8
    for (int i = 0; i < 128; i++) s += p[(size_t)i * CC];
    g_part[(b * 8 + q) * CC + c] = s;
}
__global__ void k_colsum_reduce() {
    int b = blockIdx.x, c = threadIdx.x;
    float s = 0.f;
#pragma unroll
    for (int q = 0; q < 8; q++) s += g_part[(b * 8 + q) * CC + c];
    g_s0[b * CC + c] = s * (1.0f / 32.0f);
}

// ---- caps: out = squash(S @ W_n), V = out @ W_n^T -----------------------
// grid (n=32, bg=2), 256 thr. Per block: 16 b rows, W_n slice in smem once.
#define CAPS_BL 16
#define CAPS_SM ((256 * 65 + CAPS_BL * 256 + CAPS_BL * 65) * 4)
__global__ __launch_bounds__(256, 2) void k_caps(const float* __restrict__ W,
                                                 int mode, float* __restrict__ dout) {
    extern __shared__ float sm[];
    float* sW = sm;                      // [256][65]
    float* sS = sm + 256 * 65;           // [16][256]
    float* sO = sS + CAPS_BL * 256;      // [16][65]
    int n = blockIdx.x, bg = blockIdx.y;
    int t = threadIdx.x, lane = t & 31, w = t >> 5;

    // W_n slice (256c x 64d), coalesced rows
#pragma unroll
    for (int r = 0; r < 32; r++) {
        int c = w + 8 * r;
        const float* wp = W + (size_t)c * ND + n * DD;
        sW[c * 65 + lane] = wp[lane];
        sW[c * 65 + lane + 32] = wp[lane + 32];
    }
    // S rows (sum split-K partials, or uniform s0)
#pragma unroll
    for (int bl = 0; bl < CAPS_BL; bl++) {
        int b = bg * CAPS_BL + bl;
        float s;
        if (mode == 0) s = g_s0[b * CC + t];
        else {
            s = 0.f;
#pragma unroll
            for (int q = 0; q < 8; q++)
                s += g_Spart[(size_t)((b * 8 + q) * NN + n) * CC + t];
        }
        sS[bl * CC + t] = s;
    }
    __syncthreads();

    // phase A: O[bl][d] = sum_c S[bl][c] W[c][d]   (warp w -> bl = w, w+8)
    float accA[2][2] = {};
    for (int k = 0; k < CC; k++) {
        float b0 = sW[k * 65 + lane], b1 = sW[k * 65 + lane + 32];
#pragma unroll
        for (int p = 0; p < 2; p++) {
            float a = sS[(w + 8 * p) * CC + k];
            accA[p][0] += a * b0; accA[p][1] += a * b1;
        }
    }
#pragma unroll
    for (int p = 0; p < 2; p++) {
        sO[(w + 8 * p) * 65 + lane] = accA[p][0];
        sO[(w + 8 * p) * 65 + lane + 32] = accA[p][1];
    }
    __syncwarp();

    // squash (row 64-norm), optional final output write
#pragma unroll
    for (int p = 0; p < 2; p++) {
        int bl = w + 8 * p;
        float x0 = sO[bl * 65 + lane], x1 = sO[bl * 65 + lane + 32];
        float sq = x0 * x0 + x1 * x1;
#pragma unroll
        for (int off = 16; off; off >>= 1) sq += __shfl_xor_sync(0xffffffffu, sq, off);
        float f = rsqrtf(sq + 1e-7f);
        x0 *= f; x1 *= f;
        sO[bl * 65 + lane] = x0; sO[bl * 65 + lane + 32] = x1;
        if (mode == 2) {
            int b = bg * CAPS_BL + bl;
            dout[(size_t)(b * NN + n) * DD + lane] = x0;
            dout[(size_t)(b * NN + n) * DD + lane + 32] = x1;
        }
    }
    if (mode == 2) return;
    __syncthreads();

    // phase B: V[bl][c] = sum_d O[bl][d] W[c][d]
    float accB[2][8] = {};
    for (int k = 0; k < DD; k++) {
        float bv[8];
#pragma unroll
        for (int q = 0; q < 8; q++) bv[q] = sW[(lane + 32 * q) * 65 + k];
#pragma unroll
        for (int p = 0; p < 2; p++) {
            float a = sO[(w + 8 * p) * 65 + k];
#pragma unroll
            for (int q = 0; q < 8; q++) accB[p][q] += a * bv[q];
        }
    }
#pragma unroll
    for (int p = 0; p < 2; p++) {
        int b = bg * CAPS_BL + w + 8 * p;
#pragma unroll
        for (int q = 0; q < 8; q++)
            g_V[(size_t)(b * NN + n) * CC + lane + 32 * q] = accB[p][q];
    }
}

// ---- fused routing pass: blog -> softmax -> Spart -----------------------
// grid (chunk=8, b=32), 256 thr, dynamic smem.
// warp w owns n-quad 4w..4w+3 as two n-pairs (f32x2 accumulators).
#define FUSED_SM ((8192 + 32 * 257 + 4096) * 4)
__global__ __launch_bounds__(256, 2) void k_fused(const float* __restrict__ u) {
    extern __shared__ float sm[];
    ull* sVp = (ull*)sm;                       // [16 npair][256 k]
    float* sU = sm + 8192;                     // [32][257]
    ull* sCp = (ull*)(sm + 8192 + 32 * 257);   // [16 npair][128 i]

    int chunk = blockIdx.x, b = blockIdx.y;
    int t = threadIdx.x, lane = t & 31, w = t >> 5;
    int i0 = chunk * 128;
    const float* Ub = u + (size_t)b * II * CC;
    const float* Vb = g_V + (size_t)b * NN * CC;

    // pack V -> (V[2np][k], V[2np+1][k]) pairs
    float* sVf = (float*)sVp;
#pragma unroll
    for (int n = 0; n < 32; n++)
        sVf[((n >> 1) * 256 + t) * 2 + (n & 1)] = Vb[n * CC + t];

    // phase 1: blog tile 32n x 128i
    ull acc1[2][4] = {};
    for (int kb = 0; kb < CC; kb += 32) {
        __syncthreads();
#pragma unroll
        for (int r = 0; r < 16; r++) {
            int i = w + 8 * r;
            sU[lane * 257 + i] = Ub[(size_t)(i0 + i) * CC + kb + lane];  // sU[k][i]
        }
        __syncthreads();
#pragma unroll
        for (int k2 = 0; k2 < 32; k2++) {
            ull a0 = sVp[(2 * w) * 256 + kb + k2];
            ull a1 = sVp[(2 * w + 1) * 256 + kb + k2];
#pragma unroll
            for (int q = 0; q < 4; q++) {
                ull bb = pack2(sU[k2 * 257 + lane + 32 * q]);
                fma2(acc1[0][q], a0, bb);
                fma2(acc1[1][q], a1, bb);
            }
        }
    }
#pragma unroll
    for (int jj = 0; jj < 2; jj++)
#pragma unroll
        for (int q = 0; q < 4; q++)
            sCp[(2 * w + jj) * 128 + lane + 32 * q] = acc1[jj][q];
    __syncthreads();

    // softmax over n (32 values per i), in place in sCp
    if (t < 128) {
        float v[32];
#pragma unroll
        for (int np = 0; np < 16; np++) {
            float2 p = unpack2(sCp[np * 128 + t]);
            v[2 * np] = p.x; v[2 * np + 1] = p.y;
        }
        float m = v[0];
#pragma unroll
        for (int j = 1; j < 32; j++) m = fmaxf(m, v[j]);
        float s = 0.f;
#pragma unroll
        for (int j = 0; j < 32; j++) { v[j] = __expf(v[j] - m); s += v[j]; }
        float inv = 1.0f / s;
#pragma unroll
        for (int np = 0; np < 16; np++)
            sCp[np * 128 + t] = pack2b(v[2 * np] * inv, v[2 * np + 1] * inv);
    }

    // phase 2: Spart[n][c] = sum_{i in chunk} c[n][i] u[i][c]
    ull acc2[2][8] = {};
    for (int ib = 0; ib < 128; ib += 32) {
        __syncthreads();
#pragma unroll
        for (int r = 0; r < 4; r++) {
            int k = w + 8 * r;
            const float* up = Ub + (size_t)(i0 + ib + k) * CC;
#pragma unroll
            for (int q = 0; q < 8; q++)
                sU[k * 257 + lane + 32 * q] = up[lane + 32 * q];  // sU[i][c]
        }
        __syncthreads();
#pragma unroll
        for (int k2 = 0; k2 < 32; k2++) {
            ull a0 = sCp[(2 * w) * 128 + ib + k2];
            ull a1 = sCp[(2 * w + 1) * 128 + ib + k2];
#pragma unroll
            for (int q = 0; q < 8; q++) {
                ull bb = pack2(sU[k2 * 257 + lane + 32 * q]);
                fma2(acc2[0][q], a0, bb);
                fma2(acc2[1][q], a1, bb);
            }
        }
    }
    float* Sp = g_Spart + (size_t)((b * 8 + chunk) * NN) * CC;
#pragma unroll
    for (int jj = 0; jj < 2; jj++)
#pragma unroll
        for (int q = 0; q < 8; q++) {
            float2 p = unpack2(acc2[jj][q]);
            Sp[(4 * w + 2 * jj) * CC + lane + 32 * q] = p.x;
            Sp[(4 * w + 2 * jj + 1) * CC + lane + 32 * q] = p.y;
        }
}

// ---------------------------------------------------------------------------
extern "C" void kernel_launch(void* const* d_in, const int* in_sizes, int n_in,
                              void* d_out, int out_size) {
    const float* u = (const float*)d_in[0];
    const float* W = (const float*)d_in[1];
    if (n_in >= 2 && in_sizes[0] == CC * ND) {   // defensive order check
        u = (const float*)d_in[1];
        W = (const float*)d_in[0];
    }
    float* out = (float*)d_out;

    cudaFuncSetAttribute(k_fused, cudaFuncAttributeMaxDynamicSharedMemorySize, FUSED_SM);
    cudaFuncSetAttribute(k_caps, cudaFuncAttributeMaxDynamicSharedMemorySize, CAPS_SM);

    k_colsum_part<<<dim3(8, BB), 256>>>(u);
    k_colsum_reduce<<<BB, 256>>>();
    k_caps<<<dim3(NN, 2), 256, CAPS_SM>>>(W, 0, nullptr);    // out0 -> V0

    k_fused<<<dim3(8, BB), 256, FUSED_SM>>>(u);              // pass 1
    k_caps<<<dim3(NN, 2), 256, CAPS_SM>>>(W, 1, nullptr);    // out1 -> V1
    k_fused<<<dim3(8, BB), 256, FUSED_SM>>>(u);              // pass 2
    k_caps<<<dim3(NN, 2), 256, CAPS_SM>>>(W, 2, out);        // final outputs
}